// round 1
// baseline (speedup 1.0000x reference)
#include <cuda_runtime.h>

// YOLOv7 head post-process, P3 level.
// Input:  [B=16, A*(5+NC)=255, H=80, W=80] fp32  (channel-major, stride HW between channels)
// Output: [B=16, A*H*W=19200, 85] fp32           (channel-minor, contiguous 85 per cell)
//
// Strategy: HBM-bound streaming transpose. Each block: 32 cells x 85 channels.
//  - coalesced strided-channel reads (cell = lane-fast index)
//  - smem staging at [cell*85 + c] (85 odd -> bank-conflict-free)
//  - coalesced float4 drain of the contiguous 2720-float output region.

#define NB   16
#define NA   3
#define NC_  80
#define CH   85          // 5 + NC
#define HH   80
#define WW   80
#define HW   (HH * WW)   // 6400
#define CELLS 32
#define THREADS 256
#define STRIDE 8.0f      // 640/80

__device__ __forceinline__ float fsigmoid(float x) {
    return __fdividef(1.0f, 1.0f + __expf(-x));
}

__global__ __launch_bounds__(THREADS)
void yolo_head_kernel(const float* __restrict__ in,
                      const float* __restrict__ anchors,
                      float* __restrict__ out) {
    __shared__ float s[CELLS * CH];   // 2720 floats = 10.6 KB

    const int groups_per_map = HW / CELLS;       // 200
    int bid   = blockIdx.x;
    int group = bid % groups_per_map;
    int a     = (bid / groups_per_map) % NA;
    int b     = bid / (NA * groups_per_map);
    int pos0  = group * CELLS;

    const float* ib = in + ((size_t)b * NA + a) * ((size_t)CH * HW);
    float aw = anchors[a * 2 + 0];
    float ah = anchors[a * 2 + 1];

    // ---- compute phase: read strided channels (coalesced across cells) ----
    #pragma unroll 4
    for (int i = threadIdx.x; i < CELLS * CH; i += THREADS) {
        int cell = i & (CELLS - 1);      // lane-fast -> coalesced LDG
        int c    = i >> 5;               // uniform per warp-iteration -> no divergence
        float v  = ib[(size_t)c * HW + pos0 + cell];
        float r;
        if (c == 0) {
            int gx = (pos0 + cell) % WW;
            r = (fsigmoid(v) + (float)gx) * STRIDE;
        } else if (c == 1) {
            int gy = (pos0 + cell) / WW;
            r = (fsigmoid(v) + (float)gy) * STRIDE;
        } else if (c == 2) {
            r = __expf(fminf(fmaxf(v, -16.0f), 16.0f)) * aw;
        } else if (c == 3) {
            r = __expf(fminf(fmaxf(v, -16.0f), 16.0f)) * ah;
        } else {
            r = fsigmoid(v);             // conf + 80 class scores
        }
        s[cell * CH + c] = r;            // stride-85: odd -> conflict-free banks
    }
    __syncthreads();

    // ---- drain phase: contiguous 2720-float region, vectorized stores ----
    float4* ob = (float4*)(out + (size_t)((b * NA + a) * HW + pos0) * CH);
    const float4* s4 = (const float4*)s;
    #pragma unroll 2
    for (int j = threadIdx.x; j < (CELLS * CH) / 4; j += THREADS) {
        ob[j] = s4[j];
    }
}

extern "C" void kernel_launch(void* const* d_in, const int* in_sizes, int n_in,
                              void* d_out, int out_size) {
    const float* in      = (const float*)d_in[0];
    const float* anchors = (const float*)d_in[1];
    float* out           = (float*)d_out;

    int grid = NB * NA * (HW / CELLS);   // 16 * 3 * 200 = 9600 blocks
    yolo_head_kernel<<<grid, THREADS>>>(in, anchors, out);
}

// round 2
// speedup vs baseline: 1.2370x; 1.2370x over previous
#include <cuda_runtime.h>

// YOLOv7 head post-process, P3 level — R2: float4 loads + tanh-sigmoid.
// Input:  [16, 255, 80, 80] fp32 (channel stride 6400)
// Output: [16, 19200, 85] fp32  (85 contiguous per cell)
//
// Block = 32 cells x 85 channels.
//   load : LDG.128, lanes 8-per-channel over 4 channels -> 4x 128B segments/warp
//   smem : scatter s[cell*85 + c]; bank = (20q mod 32)+cq -> all 32 banks, conflict-free
//   drain: contiguous float4 stores of the 2720-float output tile

#define NA      3
#define CH      85
#define HW      6400
#define WW      80
#define CELLS   32
#define THREADS 256
#define NV      (CH * (CELLS / 4))   // 680 float4 per tile
#define STRIDE  8.0f

__device__ __forceinline__ float fsigmoid(float x) {
    float y;
    asm("tanh.approx.f32 %0, %1;" : "=f"(y) : "f"(0.5f * x));
    return fmaf(0.5f, y, 0.5f);
}

__global__ __launch_bounds__(THREADS)
void yolo_head_kernel(const float* __restrict__ in,
                      const float* __restrict__ anchors,
                      float* __restrict__ out) {
    __shared__ float s[CELLS * CH];   // 10.6 KB

    const int groups = HW / CELLS;    // 200
    int bid   = blockIdx.x;
    int group = bid % groups;
    int a     = (bid / groups) % NA;
    int b     = bid / (NA * groups);
    int pos0  = group * CELLS;

    const float* ib = in + (size_t)(b * NA + a) * (CH * HW) + pos0;
    float aw = anchors[2 * a + 0];
    float ah = anchors[2 * a + 1];

    // ---- load + compute phase: float4 per channel-row chunk ----
    #pragma unroll 2
    for (int i = threadIdx.x; i < NV; i += THREADS) {
        int c = i >> 3;                          // channel (uniform per 8 lanes)
        int q = i & 7;                           // which float4 within the 32-cell row
        float4 v = *(const float4*)(ib + (size_t)c * HW + 4 * q);
        float vv[4] = {v.x, v.y, v.z, v.w};
        #pragma unroll
        for (int k = 0; k < 4; k++) {
            int cell = 4 * q + k;
            float x = vv[k];
            float t;
            if (c >= 4) {                        // conf + 80 classes: the hot path
                t = fsigmoid(x);
            } else if (c == 0) {
                int gx = (pos0 + cell) % WW;
                t = (fsigmoid(x) + (float)gx) * STRIDE;
            } else if (c == 1) {
                int gy = (pos0 + cell) / WW;
                t = (fsigmoid(x) + (float)gy) * STRIDE;
            } else if (c == 2) {
                t = __expf(fminf(fmaxf(x, -16.0f), 16.0f)) * aw;
            } else {                             // c == 3
                t = __expf(fminf(fmaxf(x, -16.0f), 16.0f)) * ah;
            }
            s[cell * CH + c] = t;                // conflict-free scatter
        }
    }
    __syncthreads();

    // ---- drain phase: contiguous, vectorized ----
    float4* ob = (float4*)(out + (size_t)((b * NA + a) * HW + pos0) * CH);
    const float4* s4 = (const float4*)s;
    #pragma unroll 2
    for (int j = threadIdx.x; j < NV; j += THREADS) {
        ob[j] = s4[j];
    }
}

extern "C" void kernel_launch(void* const* d_in, const int* in_sizes, int n_in,
                              void* d_out, int out_size) {
    const float* in      = (const float*)d_in[0];
    const float* anchors = (const float*)d_in[1];
    float* out           = (float*)d_out;

    int grid = 16 * NA * (HW / CELLS);   // 9600 blocks
    yolo_head_kernel<<<grid, THREADS>>>(in, anchors, out);
}

// round 3
// speedup vs baseline: 1.4809x; 1.1971x over previous
#include <cuda_runtime.h>
#include <cstdint>

// YOLOv7 head post-process — R3: uniform 5x LDG.128 loads + TMA bulk-store drain.
// Input:  [16, 255, 80, 80] fp32 (channel stride 6400)
// Output: [16, 19200, 85] fp32  (85 contiguous per cell)
//
// Block (128 thr) = 32 cells x 85 channels tile.
//   bulk loads : c=5..84 -> 640 float4 = exactly 5 LDG.128/thread (uniform, unrolled)
//   special    : c=0..4  -> 40 float4, tid<40
//   smem       : s[cell*85 + c]; banks (20q+21k+cq) cover all 32 -> conflict-free
//   drain      : ONE cp.async.bulk (10,880 B contiguous smem -> gmem) per block

#define NA      3
#define CH      85
#define HW      6400
#define WW      80
#define CELLS   32
#define THREADS 128
#define STRIDE  8.0f

__device__ __forceinline__ float fsigmoid(float x) {
    float y;
    asm("tanh.approx.f32 %0, %1;" : "=f"(y) : "f"(0.5f * x));
    return fmaf(0.5f, y, 0.5f);
}

__global__ __launch_bounds__(THREADS)
void yolo_head_kernel(const float* __restrict__ in,
                      const float* __restrict__ anchors,
                      float* __restrict__ out) {
    __shared__ __align__(16) float s[CELLS * CH];   // 10,880 B, output layout

    const int groups = HW / CELLS;    // 200
    int bid   = blockIdx.x;
    int group = bid % groups;
    int a     = (bid / groups) % NA;
    int b     = bid / (NA * groups);
    int pos0  = group * CELLS;
    int tid   = threadIdx.x;

    const float* ib = in + (size_t)(b * NA + a) * (CH * HW) + pos0;

    // ---- bulk channels 5..84: exactly 5 uniform LDG.128 per thread ----
    #pragma unroll
    for (int p = 0; p < 5; p++) {
        int i = p * THREADS + tid;           // 0..639
        int c = 5 + (i >> 3);                // channel, uniform per 8-lane octet
        int q = i & 7;                       // float4 index within 32-cell row
        float4 v = *(const float4*)(ib + (size_t)c * HW + 4 * q);
        float vv[4] = {v.x, v.y, v.z, v.w};
        #pragma unroll
        for (int k = 0; k < 4; k++)
            s[(4 * q + k) * CH + c] = fsigmoid(vv[k]);   // conflict-free scatter
    }

    // ---- special channels 0..4: 40 float4 ----
    if (tid < 40) {
        int c = tid >> 3;
        int q = tid & 7;
        float aw = anchors[2 * a + 0];
        float ah = anchors[2 * a + 1];
        float4 v = *(const float4*)(ib + (size_t)c * HW + 4 * q);
        float vv[4] = {v.x, v.y, v.z, v.w};
        #pragma unroll
        for (int k = 0; k < 4; k++) {
            int cell = 4 * q + k;
            float x = vv[k], t;
            if (c == 0)      t = (fsigmoid(x) + (float)((pos0 + cell) % WW)) * STRIDE;
            else if (c == 1) t = (fsigmoid(x) + (float)((pos0 + cell) / WW)) * STRIDE;
            else if (c == 2) t = __expf(fminf(fmaxf(x, -16.0f), 16.0f)) * aw;
            else if (c == 3) t = __expf(fminf(fmaxf(x, -16.0f), 16.0f)) * ah;
            else             t = fsigmoid(x);
            s[cell * CH + c] = t;
        }
    }
    __syncthreads();

    // ---- drain: single TMA bulk store of the contiguous tile ----
    if (tid == 0) {
        asm volatile("fence.proxy.async.shared::cta;" ::: "memory");
        uint32_t saddr;
        asm("{ .reg .u64 t; cvta.to.shared.u64 t, %1; cvt.u32.u64 %0, t; }"
            : "=r"(saddr) : "l"(s));
        uint64_t gaddr = (uint64_t)(out + (size_t)((b * NA + a) * HW + pos0) * CH);
        asm volatile(
            "cp.async.bulk.global.shared::cta.bulk_group [%0], [%1], %2;"
            :: "l"(gaddr), "r"(saddr), "n"(CELLS * CH * 4) : "memory");
        asm volatile("cp.async.bulk.commit_group;" ::: "memory");
        asm volatile("cp.async.bulk.wait_group 0;" ::: "memory");
    }
}

extern "C" void kernel_launch(void* const* d_in, const int* in_sizes, int n_in,
                              void* d_out, int out_size) {
    const float* in      = (const float*)d_in[0];
    const float* anchors = (const float*)d_in[1];
    float* out           = (float*)d_out;

    int grid = 16 * NA * (HW / CELLS);   // 9600 blocks
    yolo_head_kernel<<<grid, THREADS>>>(in, anchors, out);
}

// round 4
// speedup vs baseline: 1.4923x; 1.0077x over previous
#include <cuda_runtime.h>
#include <cstdint>

// YOLOv7 head post-process — R4: 64-cell tiles, one TMA bulk store per block.
// Input:  [16, 255, 80, 80] fp32 (channel stride 6400)
// Output: [16, 19200, 85] fp32  (85 contiguous per cell)
//
// Block (256 thr) = 64 cells x 85 channels tile (21,760 B output, contiguous).
//   bulk loads : c=5..84 -> 1280 float4 = exactly 5 LDG.128/thread (uniform, unrolled)
//   special    : c=0..4  -> 80 float4, tid<80
//   smem       : s[cell*85 + c] in exact output layout
//   drain      : ONE cp.async.bulk (21,760 B) per block

#define NA      3
#define CH      85
#define HW      6400
#define WW      80
#define CELLS   64
#define THREADS 256
#define STRIDE  8.0f

__device__ __forceinline__ float fsigmoid(float x) {
    float y;
    asm("tanh.approx.f32 %0, %1;" : "=f"(y) : "f"(0.5f * x));
    return fmaf(0.5f, y, 0.5f);
}

__global__ __launch_bounds__(THREADS)
void yolo_head_kernel(const float* __restrict__ in,
                      const float* __restrict__ anchors,
                      float* __restrict__ out) {
    __shared__ __align__(16) float s[CELLS * CH];   // 21,760 B, output layout

    const int groups = HW / CELLS;    // 100
    int bid   = blockIdx.x;
    int group = bid % groups;
    int a     = (bid / groups) % NA;
    int b     = bid / (NA * groups);
    int pos0  = group * CELLS;
    int tid   = threadIdx.x;

    const float* ib = in + (size_t)(b * NA + a) * (CH * HW) + pos0;

    // ---- bulk channels 5..84: exactly 5 uniform LDG.128 per thread ----
    #pragma unroll
    for (int p = 0; p < 5; p++) {
        int i = p * THREADS + tid;           // 0..1279
        int c = 5 + (i >> 4);                // channel, uniform per 16-lane group
        int q = i & 15;                      // float4 index within 64-cell row
        float4 v = *(const float4*)(ib + (size_t)c * HW + 4 * q);
        float vv[4] = {v.x, v.y, v.z, v.w};
        #pragma unroll
        for (int k = 0; k < 4; k++)
            s[(4 * q + k) * CH + c] = fsigmoid(vv[k]);
    }

    // ---- special channels 0..4: 80 float4 ----
    if (tid < 80) {
        int c = tid >> 4;
        int q = tid & 15;
        float aw = anchors[2 * a + 0];
        float ah = anchors[2 * a + 1];
        float4 v = *(const float4*)(ib + (size_t)c * HW + 4 * q);
        float vv[4] = {v.x, v.y, v.z, v.w};
        #pragma unroll
        for (int k = 0; k < 4; k++) {
            int cell = 4 * q + k;
            float x = vv[k], t;
            if (c == 0)      t = (fsigmoid(x) + (float)((pos0 + cell) % WW)) * STRIDE;
            else if (c == 1) t = (fsigmoid(x) + (float)((pos0 + cell) / WW)) * STRIDE;
            else if (c == 2) t = __expf(fminf(fmaxf(x, -16.0f), 16.0f)) * aw;
            else if (c == 3) t = __expf(fminf(fmaxf(x, -16.0f), 16.0f)) * ah;
            else             t = fsigmoid(x);
            s[cell * CH + c] = t;
        }
    }
    __syncthreads();

    // ---- drain: single TMA bulk store of the contiguous 64-cell tile ----
    if (tid == 0) {
        asm volatile("fence.proxy.async.shared::cta;" ::: "memory");
        uint32_t saddr;
        asm("{ .reg .u64 t; cvta.to.shared.u64 t, %1; cvt.u32.u64 %0, t; }"
            : "=r"(saddr) : "l"(s));
        uint64_t gaddr = (uint64_t)(out + (size_t)((b * NA + a) * HW + pos0) * CH);
        asm volatile(
            "cp.async.bulk.global.shared::cta.bulk_group [%0], [%1], %2;"
            :: "l"(gaddr), "r"(saddr), "n"(CELLS * CH * 4) : "memory");
        asm volatile("cp.async.bulk.commit_group;" ::: "memory");
        asm volatile("cp.async.bulk.wait_group 0;" ::: "memory");
    }
}

extern "C" void kernel_launch(void* const* d_in, const int* in_sizes, int n_in,
                              void* d_out, int out_size) {
    const float* in      = (const float*)d_in[0];
    const float* anchors = (const float*)d_in[1];
    float* out           = (float*)d_out;

    int grid = 16 * NA * (HW / CELLS);   // 4800 blocks
    yolo_head_kernel<<<grid, THREADS>>>(in, anchors, out);
}